// round 10
// baseline (speedup 1.0000x reference)
#include <cuda_runtime.h>
#include <cstdint>

#define S_LEN 2048
#define DK 64
#define BM 128
#define BN 64
#define NBH 32
#define CTX_ELEMS ((size_t)NBH * S_LEN * DK)

#define RS 144   // smem row stride in bytes -> conflict-free LDSM

// smem map: Q hi/lo fixed; K/V double-buffered stages
#define OFF_QHI 0
#define OFF_QLO (BM * RS)
#define STAGE_BASE (2 * BM * RS)
#define ST_KHI 0
#define ST_KLO (BN * RS)
#define ST_VHI (2 * BN * RS)
#define ST_VLO (3 * BN * RS)
#define STAGE_SZ (4 * BN * RS)                  // 36864
#define SMEM_TOTAL (STAGE_BASE + 2 * STAGE_SZ)  // 110592 -> 2 CTAs/SM

__device__ float g_lsum[NBH * S_LEN];

// ---------------------------------------------------------------------------
// helpers
// ---------------------------------------------------------------------------
__device__ __forceinline__ uint32_t smem_u32(const void* p) {
    uint32_t a;
    asm("{ .reg .u64 t; cvta.to.shared.u64 t, %1; cvt.u32.u64 %0, t; }"
        : "=r"(a) : "l"(p));
    return a;
}

__device__ __forceinline__ void ldsm_x4(uint32_t* r, uint32_t addr) {
    asm volatile("ldmatrix.sync.aligned.m8n8.x4.shared.b16 {%0,%1,%2,%3}, [%4];"
        : "=r"(r[0]), "=r"(r[1]), "=r"(r[2]), "=r"(r[3]) : "r"(addr));
}
__device__ __forceinline__ void ldsm_x4t(uint32_t* r, uint32_t addr) {
    asm volatile("ldmatrix.sync.aligned.m8n8.x4.trans.shared.b16 {%0,%1,%2,%3}, [%4];"
        : "=r"(r[0]), "=r"(r[1]), "=r"(r[2]), "=r"(r[3]) : "r"(addr));
}

// pack two f32 -> bf16x2 (a -> low half, b -> high half)
__device__ __forceinline__ uint32_t bf2(float a, float b) {
    uint32_t r;
    asm("cvt.rn.bf16x2.f32 %0, %1, %2;" : "=r"(r) : "f"(b), "f"(a));
    return r;
}
__device__ __forceinline__ float bflo(uint32_t p) { return __uint_as_float(p << 16); }
__device__ __forceinline__ float bfhi(uint32_t p) { return __uint_as_float(p & 0xffff0000u); }

// m16n8k16 bf16 mma, D=C (accumulate in-place)
__device__ __forceinline__ void mma16816(float* c, const uint32_t* a, const uint32_t* b) {
    asm volatile(
        "mma.sync.aligned.m16n8k16.row.col.f32.bf16.bf16.f32 "
        "{%0,%1,%2,%3}, {%4,%5,%6,%7}, {%8,%9}, {%0,%1,%2,%3};"
        : "+f"(c[0]), "+f"(c[1]), "+f"(c[2]), "+f"(c[3])
        : "r"(a[0]), "r"(a[1]), "r"(a[2]), "r"(a[3]), "r"(b[0]), "r"(b[1]));
}

// convert 8 f32 (two float4) -> hi/lo bf16 16B chunks, store linear
__device__ __forceinline__ void cvt_store8(float4 a, float4 b, char* hi_base,
                                           char* lo_base, uint32_t byte_off) {
    float x[8] = {a.x, a.y, a.z, a.w, b.x, b.y, b.z, b.w};
    uint4 hi4, lo4;
    uint32_t* hp = (uint32_t*)&hi4;
    uint32_t* lp = (uint32_t*)&lo4;
    #pragma unroll
    for (int i = 0; i < 4; i++) {
        uint32_t h = bf2(x[2 * i], x[2 * i + 1]);
        hp[i] = h;
        lp[i] = bf2(x[2 * i] - bflo(h), x[2 * i + 1] - bfhi(h));
    }
    *(uint4*)(hi_base + byte_off) = hi4;
    *(uint4*)(lo_base + byte_off) = lo4;
}

// ---------------------------------------------------------------------------
// Pass 1: mma.sync flash attention; unnormalized attn + normalized context.
// CTA = 256 threads (8 warps); warp w owns rows [w*16, w*16+16). K/V smem
// double-buffered: ONE __syncthreads per key tile.
// ---------------------------------------------------------------------------
__global__ __launch_bounds__(256, 2)
void attn_pass1(const float* __restrict__ Qg, const float* __restrict__ Kg,
                const float* __restrict__ Vg, float* __restrict__ out)
{
    extern __shared__ char smc[];
    const uint32_t smb = smem_u32(smc);
    const int tid  = threadIdx.x;
    const int wid  = tid >> 5;
    const int lane = tid & 31;
    const int r    = lane >> 2;     // C/A fragment row-in-group
    const int q    = lane & 3;      // fragment col-group

    const int bh   = blockIdx.y;
    const int qb   = (int)gridDim.x - 1 - (int)blockIdx.x;  // heavy blocks first
    const int row0 = qb * BM;
    const int mrow = wid * 16;

    const float* Qbh = Qg + (size_t)bh * S_LEN * DK;
    const float* Kbh = Kg + (size_t)bh * S_LEN * DK;
    const float* Vbh = Vg + (size_t)bh * S_LEN * DK;
    float* ctx  = out + (size_t)bh * S_LEN * DK;
    float* attn = out + CTX_ELEMS + (size_t)bh * S_LEN * S_LEN;

    // per-lane ldmatrix base offsets
    const uint32_t aQbase = (uint32_t)((mrow + (lane & 15)) * RS + (lane >> 4) * 16);
    const uint32_t bKbase = (uint32_t)(((lane >> 4) * 8 + (lane & 7)) * RS
                                       + ((lane >> 3) & 1) * 16);
    const uint32_t bVbase = (uint32_t)((((lane >> 3) & 1) * 8 + (lane & 7)) * RS
                                       + (lane >> 4) * 16);

    // K/V gmem positions for this thread (4 threads per row, 16 floats each)
    const int ld_row = tid >> 2;
    const int ld_qt  = tid & 3;
    const int nkb    = 2 * qb + 2;

    float4 kf[4], vf[4];            // in-flight f32 K/V for next tile

    // ---- prologue: convert Q tile; load+store K/V tile 0; prefetch tile 1 ----
    {
        int row = tid >> 1, half = tid & 1;
        const float* qrow = Qbh + (size_t)(row0 + row) * DK + half * 32;
        #pragma unroll
        for (int g = 0; g < 4; g++) {
            float4 a = __ldg((const float4*)(qrow + g * 8));
            float4 b = __ldg((const float4*)(qrow + g * 8 + 4));
            cvt_store8(a, b, smc + OFF_QHI, smc + OFF_QLO,
                       (uint32_t)(row * RS + half * 64 + g * 16));
        }
    }
    {
        const float* krow = Kbh + (size_t)ld_row * DK + ld_qt * 16;
        const float* vrow = Vbh + (size_t)ld_row * DK + ld_qt * 16;
        #pragma unroll
        for (int g = 0; g < 4; g++) {
            kf[g] = __ldg((const float4*)(krow + g * 4));
            vf[g] = __ldg((const float4*)(vrow + g * 4));
        }
        char* st0 = smc + STAGE_BASE;                  // stage 0
        uint32_t off = (uint32_t)(ld_row * RS + ld_qt * 32);
        cvt_store8(kf[0], kf[1], st0 + ST_KHI, st0 + ST_KLO, off);
        cvt_store8(kf[2], kf[3], st0 + ST_KHI, st0 + ST_KLO, off + 16);
        cvt_store8(vf[0], vf[1], st0 + ST_VHI, st0 + ST_VLO, off);
        cvt_store8(vf[2], vf[3], st0 + ST_VHI, st0 + ST_VLO, off + 16);
        // prefetch tile 1 (nkb >= 2 always)
        const float* krow1 = krow + (size_t)BN * DK;
        const float* vrow1 = vrow + (size_t)BN * DK;
        #pragma unroll
        for (int g = 0; g < 4; g++) {
            kf[g] = __ldg((const float4*)(krow1 + g * 4));
            vf[g] = __ldg((const float4*)(vrow1 + g * 4));
        }
    }

    float oacc[8][4];
    #pragma unroll
    for (int j = 0; j < 8; j++) {
        oacc[j][0] = 0.f; oacc[j][1] = 0.f; oacc[j][2] = 0.f; oacc[j][3] = 0.f;
    }
    float lsum0 = 0.f, lsum1 = 0.f;
    const int grow0  = row0 + mrow + r;         // this thread's first row
    const int rowmax = row0 + mrow + 15;        // warp band's last row

    for (int jb = 0; jb < nkb; jb++) {
        const int c0 = jb * BN;

        __syncthreads();   // tile jb smem visible; all done reading other stage

        // ---- stage tile jb+1 into the other buffer (no barrier needed) ----
        if (jb + 1 < nkb) {
            char* st = smc + STAGE_BASE + ((jb + 1) & 1) * STAGE_SZ;
            uint32_t off = (uint32_t)(ld_row * RS + ld_qt * 32);
            cvt_store8(kf[0], kf[1], st + ST_KHI, st + ST_KLO, off);
            cvt_store8(kf[2], kf[3], st + ST_KHI, st + ST_KLO, off + 16);
            cvt_store8(vf[0], vf[1], st + ST_VHI, st + ST_VLO, off);
            cvt_store8(vf[2], vf[3], st + ST_VHI, st + ST_VLO, off + 16);
        }

        const uint32_t sb = smb + STAGE_BASE + (uint32_t)((jb & 1) * STAGE_SZ);
        const bool active = (c0 <= rowmax);

        // ---- S = Q @ K^T (split-bf16, 3 terms) ----
        float sacc[8][4];
        if (active) {
            #pragma unroll
            for (int j = 0; j < 8; j++) {
                sacc[j][0] = 0.f; sacc[j][1] = 0.f; sacc[j][2] = 0.f; sacc[j][3] = 0.f;
            }
            #pragma unroll
            for (int ks = 0; ks < 4; ks++) {
                uint32_t ah[4], al[4];
                ldsm_x4(ah, smb + OFF_QHI + aQbase + ks * 32);
                ldsm_x4(al, smb + OFF_QLO + aQbase + ks * 32);
                #pragma unroll
                for (int jp = 0; jp < 4; jp++) {
                    uint32_t kh[4], kl[4];
                    uint32_t boff = bKbase + (uint32_t)(jp * 16 * RS + ks * 32);
                    ldsm_x4(kh, sb + ST_KHI + boff);
                    ldsm_x4(kl, sb + ST_KLO + boff);
                    mma16816(sacc[2 * jp],     ah, kh);
                    mma16816(sacc[2 * jp + 1], ah, kh + 2);
                    mma16816(sacc[2 * jp],     ah, kl);
                    mma16816(sacc[2 * jp + 1], ah, kl + 2);
                    mma16816(sacc[2 * jp],     al, kh);
                    mma16816(sacc[2 * jp + 1], al, kh + 2);
                }
            }
        }

        // ---- prefetch tile jb+2 (unconditional; hidden by PV phase) ----
        if (jb + 2 < nkb) {
            const float* krow = Kbh + (size_t)(c0 + 2 * BN + ld_row) * DK + ld_qt * 16;
            const float* vrow = Vbh + (size_t)(c0 + 2 * BN + ld_row) * DK + ld_qt * 16;
            #pragma unroll
            for (int g = 0; g < 4; g++) {
                kf[g] = __ldg((const float4*)(krow + g * 4));
                vf[g] = __ldg((const float4*)(vrow + g * 4));
            }
        }

        if (!active) continue;

        // ---- fused epilogue + PV, per ks (= key pair-of-8 group) ----
        #pragma unroll
        for (int ks = 0; ks < 4; ks++) {
            uint32_t ah[4], al[4];
            #pragma unroll
            for (int jj = 0; jj < 2; jj++) {
                const int j  = 2 * ks + jj;
                const int cj = c0 + j * 8 + q * 2;
                float p0 = (cj     <= grow0)     ? __expf(sacc[j][0] * 0.125f) : 0.f;
                float p1 = (cj + 1 <= grow0)     ? __expf(sacc[j][1] * 0.125f) : 0.f;
                float p2 = (cj     <= grow0 + 8) ? __expf(sacc[j][2] * 0.125f) : 0.f;
                float p3 = (cj + 1 <= grow0 + 8) ? __expf(sacc[j][3] * 0.125f) : 0.f;
                lsum0 += p0 + p1;
                lsum1 += p2 + p3;
                __stcs((float2*)(attn + (size_t)grow0 * S_LEN + cj),
                       make_float2(p0, p1));
                __stcs((float2*)(attn + (size_t)(grow0 + 8) * S_LEN + cj),
                       make_float2(p2, p3));
                uint32_t h0 = bf2(p0, p1), h1 = bf2(p2, p3);
                ah[2 * jj]     = h0;
                ah[2 * jj + 1] = h1;
                al[2 * jj]     = bf2(p0 - bflo(h0), p1 - bfhi(h0));
                al[2 * jj + 1] = bf2(p2 - bflo(h1), p3 - bfhi(h1));
            }
            #pragma unroll
            for (int jp = 0; jp < 4; jp++) {
                uint32_t vh[4], vl[4];
                uint32_t boff = bVbase + (uint32_t)(ks * 16 * RS + jp * 32);
                ldsm_x4t(vh, sb + ST_VHI + boff);
                ldsm_x4t(vl, sb + ST_VLO + boff);
                mma16816(oacc[2 * jp],     ah, vh);
                mma16816(oacc[2 * jp + 1], ah, vh + 2);
                mma16816(oacc[2 * jp],     ah, vl);
                mma16816(oacc[2 * jp + 1], ah, vl + 2);
                mma16816(oacc[2 * jp],     al, vh);
                mma16816(oacc[2 * jp + 1], al, vh + 2);
            }
        }
    }

    // ---- reduce row sums within quads, normalize O, write context ----
    lsum0 += __shfl_xor_sync(0xffffffffu, lsum0, 1);
    lsum0 += __shfl_xor_sync(0xffffffffu, lsum0, 2);
    lsum1 += __shfl_xor_sync(0xffffffffu, lsum1, 1);
    lsum1 += __shfl_xor_sync(0xffffffffu, lsum1, 2);
    if (q == 0) {
        g_lsum[bh * S_LEN + grow0]     = lsum0;
        g_lsum[bh * S_LEN + grow0 + 8] = lsum1;
    }
    const float inv0 = 1.f / lsum0;
    const float inv1 = 1.f / lsum1;
    #pragma unroll
    for (int j = 0; j < 8; j++) {
        int cj = j * 8 + q * 2;
        *(float2*)(ctx + (size_t)grow0 * DK + cj) =
            make_float2(oacc[j][0] * inv0, oacc[j][1] * inv0);
        *(float2*)(ctx + (size_t)(grow0 + 8) * DK + cj) =
            make_float2(oacc[j][2] * inv1, oacc[j][3] * inv1);
    }
}

// ---------------------------------------------------------------------------
// Pass 2: attn[row, col<=row] *= 1/l(row); attn[row, col>row] = 0.
// ---------------------------------------------------------------------------
__global__ __launch_bounds__(256)
void attn_pass2(float* __restrict__ out)
{
    const int gid = blockIdx.x;               // bh*S_LEN + row
    const int r   = gid & (S_LEN - 1);
    const float inv = 1.f / g_lsum[gid];
    float4* rowp = (float4*)(out + CTX_ELEMS + (size_t)gid * S_LEN);
    const int tid = threadIdx.x;

    #pragma unroll
    for (int it = 0; it < 2; it++) {
        int c4  = tid + it * 256;
        int col = c4 << 2;
        float4 v;
        if (col + 3 <= r) {
            v = __ldcs(rowp + c4);
            v.x *= inv; v.y *= inv; v.z *= inv; v.w *= inv;
        } else if (col > r) {
            v.x = 0.f; v.y = 0.f; v.z = 0.f; v.w = 0.f;
        } else {
            v = __ldcs(rowp + c4);
            v.x = (col + 0 <= r) ? v.x * inv : 0.f;
            v.y = (col + 1 <= r) ? v.y * inv : 0.f;
            v.z = (col + 2 <= r) ? v.z * inv : 0.f;
            v.w = (col + 3 <= r) ? v.w * inv : 0.f;
        }
        __stcs(rowp + c4, v);
    }
}

extern "C" void kernel_launch(void* const* d_in, const int* in_sizes, int n_in,
                              void* d_out, int out_size)
{
    const float* Q = (const float*)d_in[0];
    const float* K = (const float*)d_in[1];
    const float* V = (const float*)d_in[2];
    float* out = (float*)d_out;

    cudaFuncSetAttribute(attn_pass1, cudaFuncAttributeMaxDynamicSharedMemorySize,
                         SMEM_TOTAL);

    dim3 grid1(S_LEN / BM, NBH);
    attn_pass1<<<grid1, 256, SMEM_TOTAL>>>(Q, K, V, out);
    attn_pass2<<<NBH * S_LEN, 256>>>(out);
}